// round 3
// baseline (speedup 1.0000x reference)
#include <cuda_runtime.h>
#include <math.h>

#define Hdim   1024
#define Edim   512
#define GATES  4096          // 4*Hdim
#define MAXS   2048
#define MAXD   512
#define G_CTAS 128           // Hdim/8 CTAs, all resident (<=148 SMs)

// ---------------- persistent device state ----------------
__device__ __align__(16) float d_Xp[(size_t)MAXS * GATES];               // encoder input projections (+bias)
__device__ __align__(16) float d_Hbuf[(size_t)(MAXS + MAXD + 1) * Hdim]; // h_t for every step (step-indexed)
__device__ int   d_cnt[MAXS + MAXD + 2];                                 // per-step arrival counters

// ---------------- init: zero counters + h0 ----------------
__global__ void init_kernel(int total_steps) {
    int i = blockIdx.x * blockDim.x + threadIdx.x;
    if (i < total_steps + 2) d_cnt[i] = 0;
    if (i < Hdim) d_Hbuf[i] = 0.0f;
}

// ---------------- Xp GEMM: Xp[t][r] = enc_Wih[r,:] . emb[state[t],:] + enc_b[r] ----------------
// NT GEMM, 128(r) x 128(t) tiles, K=512 in chunks of 16.
__global__ __launch_bounds__(256) void xp_gemm(const int* __restrict__ state,
                                               const float* __restrict__ Wih,
                                               const float* __restrict__ emb,
                                               const float* __restrict__ bih,
                                               const float* __restrict__ bhh,
                                               int S) {
    __shared__ float As[16][132];   // [k][r]
    __shared__ float Bs[16][132];   // [k][t]
    __shared__ int   toks[128];

    int bt = blockIdx.x;            // t tile
    int br = blockIdx.y;            // r tile
    int tid = threadIdx.x;

    if (tid < 128) {
        int t = bt * 128 + tid;
        toks[tid] = (t < S) ? state[t] : 0;
    }
    __syncthreads();

    int tx = tid & 15;              // t dir (8 outputs)
    int ty = tid >> 4;              // r dir (8 outputs)

    float acc[8][8];
#pragma unroll
    for (int i = 0; i < 8; i++)
#pragma unroll
        for (int j = 0; j < 8; j++) acc[i][j] = 0.0f;

    int lrow = tid & 127;           // which row of the tile this thread loads
    int kh = (tid >> 7) * 8;        // which k-half (0 or 8)

    const float* Aptr = Wih + (size_t)(br * 128 + lrow) * Edim;
    const float* Bptr = emb + (size_t)toks[lrow] * Edim;

    for (int k0 = 0; k0 < Edim; k0 += 16) {
        float4 a0 = *(const float4*)&Aptr[k0 + kh];
        float4 a1 = *(const float4*)&Aptr[k0 + kh + 4];
        float4 b0 = *(const float4*)&Bptr[k0 + kh];
        float4 b1 = *(const float4*)&Bptr[k0 + kh + 4];
        As[kh + 0][lrow] = a0.x; As[kh + 1][lrow] = a0.y;
        As[kh + 2][lrow] = a0.z; As[kh + 3][lrow] = a0.w;
        As[kh + 4][lrow] = a1.x; As[kh + 5][lrow] = a1.y;
        As[kh + 6][lrow] = a1.z; As[kh + 7][lrow] = a1.w;
        Bs[kh + 0][lrow] = b0.x; Bs[kh + 1][lrow] = b0.y;
        Bs[kh + 2][lrow] = b0.z; Bs[kh + 3][lrow] = b0.w;
        Bs[kh + 4][lrow] = b1.x; Bs[kh + 5][lrow] = b1.y;
        Bs[kh + 6][lrow] = b1.z; Bs[kh + 7][lrow] = b1.w;
        __syncthreads();

#pragma unroll
        for (int k = 0; k < 16; k++) {
            float a[8], b[8];
            *(float4*)&a[0] = *(const float4*)&As[k][ty * 8];
            *(float4*)&a[4] = *(const float4*)&As[k][ty * 8 + 4];
            *(float4*)&b[0] = *(const float4*)&Bs[k][tx * 8];
            *(float4*)&b[4] = *(const float4*)&Bs[k][tx * 8 + 4];
#pragma unroll
            for (int i = 0; i < 8; i++)
#pragma unroll
                for (int j = 0; j < 8; j++) acc[i][j] += a[i] * b[j];
        }
        __syncthreads();
    }

    // epilogue: add enc_b, store Xp[t*4096 + r]  (row stride 4096 -> 16B aligned)
    float bias[8];
#pragma unroll
    for (int i = 0; i < 8; i++) {
        int r = br * 128 + ty * 8 + i;
        bias[i] = bih[r] + bhh[r];
    }
#pragma unroll
    for (int j = 0; j < 8; j++) {
        int t = bt * 128 + tx * 8 + j;
        if (t >= S) continue;
        float* orow = d_Xp + (size_t)t * GATES + br * 128 + ty * 8;
        float4 v0 = make_float4(acc[0][j] + bias[0], acc[1][j] + bias[1],
                                acc[2][j] + bias[2], acc[3][j] + bias[3]);
        float4 v1 = make_float4(acc[4][j] + bias[4], acc[5][j] + bias[5],
                                acc[6][j] + bias[6], acc[7][j] + bias[7]);
        *(float4*)&orow[0] = v0;
        *(float4*)&orow[4] = v1;
    }
}

// ---------------- persistent recurrence kernel ----------------
// 128 CTAs x 256 threads. CTA b owns h indices [b*8, b*8+8) and gate rows
// {g*1024 + b*8 + q : g in 0..3, q in 0..7}. Thread (rl,seg): rl=tid>>3 row-local,
// seg=tid&7 owns columns [seg*128, seg*128+128) held as 32 float4 registers.
__device__ __forceinline__ float sigmoidf_(float x) { return 1.0f / (1.0f + expf(-x)); }

__global__ __launch_bounds__(256, 1) void recur(const float* __restrict__ encWhh,
                                                const float* __restrict__ decWhh,
                                                const float* __restrict__ dbih,
                                                const float* __restrict__ dbhh,
                                                int S, int D) {
    __shared__ float4 hs4[8 * 33];   // padded h (33 float4 per 32-float4 segment)
    __shared__ float  g_s[32];
    __shared__ float  c_s[8];

    int tid = threadIdx.x;
    int b = blockIdx.x;
    int seg = tid & 7;
    int rl = tid >> 3;               // 0..31
    int gate = rl >> 3, q = rl & 7;
    int R = gate * 1024 + b * 8 + q;

    if (tid < 8) c_s[tid] = 0.0f;

    float4 w[32];
    {
        const float4* src = (const float4*)(encWhh + (size_t)R * Hdim + seg * 128);
#pragma unroll
        for (int k = 0; k < 32; k++) w[k] = src[k];
    }
    float decB = 0.0f;
    if (seg == 0) decB = dbih[R] + dbhh[R];

    int TS = S + D;
    for (int t = 0; t < TS; t++) {
        if (t == S) {  // switch to decoder weights
            const float4* src = (const float4*)(decWhh + (size_t)R * Hdim + seg * 128);
#pragma unroll
            for (int k = 0; k < 32; k++) w[k] = src[k];
        }
        if (t > 0) {
            if (tid == 0) {
                int v;
                do {
                    asm volatile("ld.acquire.gpu.u32 %0, [%1];"
                                 : "=r"(v) : "l"(d_cnt + t));
                } while (v < G_CTAS);
            }
        }
        __syncthreads();

        // stage h_t into padded smem (conflict-free, one float4 per thread)
        {
            float4 hv = *(const float4*)(d_Hbuf + (size_t)t * Hdim + tid * 4);
            hs4[tid + (tid >> 5)] = hv;
        }
        // prefetch per-row additive term (Xp for encoder, const bias for decoder)
        float extra = 0.0f;
        if (seg == 0) extra = (t < S) ? d_Xp[(size_t)t * GATES + R] : decB;
        __syncthreads();

        // 128-wide partial dot from register weights
        float a0 = 0, a1 = 0, a2 = 0, a3 = 0;
#pragma unroll
        for (int k = 0; k < 32; k += 2) {
            float4 h0 = hs4[seg * 33 + k];
            float4 h1 = hs4[seg * 33 + k + 1];
            a0 += w[k].x * h0.x;  a1 += w[k].y * h0.y;
            a2 += w[k].z * h0.z;  a3 += w[k].w * h0.w;
            a0 += w[k + 1].x * h1.x;  a1 += w[k + 1].y * h1.y;
            a2 += w[k + 1].z * h1.z;  a3 += w[k + 1].w * h1.w;
        }
        float acc = (a0 + a1) + (a2 + a3);
        // reduce across 8 segs (contiguous lanes)
        acc += __shfl_xor_sync(0xffffffffu, acc, 1);
        acc += __shfl_xor_sync(0xffffffffu, acc, 2);
        acc += __shfl_xor_sync(0xffffffffu, acc, 4);
        if (seg == 0) g_s[rl] = acc + extra;
        __syncthreads();

        // LSTM cell for this CTA's 8 h-indices (warp 0, lanes 0..7)
        if (tid < 8) {
            float i_ = sigmoidf_(g_s[tid]);
            float f_ = sigmoidf_(g_s[8 + tid]);
            float g_ = tanhf(g_s[16 + tid]);
            float o_ = sigmoidf_(g_s[24 + tid]);
            float c = f_ * c_s[tid] + i_ * g_;
            c_s[tid] = c;
            float h = o_ * tanhf(c);
            d_Hbuf[(size_t)(t + 1) * Hdim + b * 8 + tid] = h;
            __threadfence();  // make h visible at gpu scope before the release
        }
        __syncwarp();
        if (tid == 0) atomicAdd(&d_cnt[t + 1], 1);
    }
}

// ---------------- output GEMM: logits[m][n] = Hdec[m,:] . Wout[n,:] + bout[n] ----------------
__global__ __launch_bounds__(256) void out_gemm(const float* __restrict__ Wout,
                                                const float* __restrict__ bout,
                                                float* __restrict__ out,
                                                int hoff, int M, int N) {
    __shared__ float As[16][132];
    __shared__ float Bs[16][132];

    int bn = blockIdx.x, bm = blockIdx.y;
    int tid = threadIdx.x;
    int tx = tid & 15;     // n dir
    int ty = tid >> 4;     // m dir

    float acc[8][8];
#pragma unroll
    for (int i = 0; i < 8; i++)
#pragma unroll
        for (int j = 0; j < 8; j++) acc[i][j] = 0.0f;

    int lrow = tid & 127;
    int kh = (tid >> 7) * 8;

    int mrow = bm * 128 + lrow; if (mrow >= M) mrow = M - 1;
    int nrow = bn * 128 + lrow; if (nrow >= N) nrow = N - 1;
    const float* Aptr = d_Hbuf + (size_t)(hoff + mrow) * Hdim;
    const float* Bptr = Wout + (size_t)nrow * Hdim;

    for (int k0 = 0; k0 < Hdim; k0 += 16) {
        float4 a0 = *(const float4*)&Aptr[k0 + kh];
        float4 a1 = *(const float4*)&Aptr[k0 + kh + 4];
        float4 b0 = *(const float4*)&Bptr[k0 + kh];
        float4 b1 = *(const float4*)&Bptr[k0 + kh + 4];
        As[kh + 0][lrow] = a0.x; As[kh + 1][lrow] = a0.y;
        As[kh + 2][lrow] = a0.z; As[kh + 3][lrow] = a0.w;
        As[kh + 4][lrow] = a1.x; As[kh + 5][lrow] = a1.y;
        As[kh + 6][lrow] = a1.z; As[kh + 7][lrow] = a1.w;
        Bs[kh + 0][lrow] = b0.x; Bs[kh + 1][lrow] = b0.y;
        Bs[kh + 2][lrow] = b0.z; Bs[kh + 3][lrow] = b0.w;
        Bs[kh + 4][lrow] = b1.x; Bs[kh + 5][lrow] = b1.y;
        Bs[kh + 6][lrow] = b1.z; Bs[kh + 7][lrow] = b1.w;
        __syncthreads();

#pragma unroll
        for (int k = 0; k < 16; k++) {
            float a[8], b[8];
            *(float4*)&a[0] = *(const float4*)&As[k][ty * 8];
            *(float4*)&a[4] = *(const float4*)&As[k][ty * 8 + 4];
            *(float4*)&b[0] = *(const float4*)&Bs[k][tx * 8];
            *(float4*)&b[4] = *(const float4*)&Bs[k][tx * 8 + 4];
#pragma unroll
            for (int i = 0; i < 8; i++)
#pragma unroll
                for (int j = 0; j < 8; j++) acc[i][j] += a[i] * b[j];
        }
        __syncthreads();
    }

    // Epilogue: N = 50257 is odd -> row base (out + m*N) is only 4B-aligned.
    // MUST use scalar stores (float4 here traps: misaligned address).
#pragma unroll
    for (int i = 0; i < 8; i++) {
        int m = bm * 128 + ty * 8 + i;
        if (m >= M) continue;
        float* orow = out + (size_t)m * N;
#pragma unroll
        for (int j = 0; j < 8; j++) {
            int n = bn * 128 + tx * 8 + j;
            if (n < N) orow[n] = acc[i][j] + bout[n];
        }
    }
}

// ---------------- row softmax (in place) ----------------
__global__ void softmax_rows(float* __restrict__ out, int N) {
    int row = blockIdx.x;
    float* p = out + (size_t)row * N;
    int tid = threadIdx.x;
    __shared__ float red[256];

    float mx = -1e30f;
    for (int i = tid; i < N; i += 256) mx = fmaxf(mx, p[i]);
    red[tid] = mx; __syncthreads();
    for (int s = 128; s > 0; s >>= 1) {
        if (tid < s) red[tid] = fmaxf(red[tid], red[tid + s]);
        __syncthreads();
    }
    mx = red[0]; __syncthreads();

    float sum = 0.0f;
    for (int i = tid; i < N; i += 256) sum += __expf(p[i] - mx);
    red[tid] = sum; __syncthreads();
    for (int s = 128; s > 0; s >>= 1) {
        if (tid < s) red[tid] += red[tid + s];
        __syncthreads();
    }
    float inv = 1.0f / red[0];

    for (int i = tid; i < N; i += 256) p[i] = __expf(p[i] - mx) * inv;
}

// ---------------- launch ----------------
extern "C" void kernel_launch(void* const* d_in, const int* in_sizes, int n_in,
                              void* d_out, int out_size) {
    const int*   state   = (const int*)d_in[0];
    // d_in[1] = max_len scalar (derived from out_size instead)
    const float* emb     = (const float*)d_in[2];
    const float* enc_Wih = (const float*)d_in[3];
    const float* enc_Whh = (const float*)d_in[4];
    const float* enc_bih = (const float*)d_in[5];
    const float* enc_bhh = (const float*)d_in[6];
    const float* dec_Whh = (const float*)d_in[8];
    const float* dec_bih = (const float*)d_in[9];
    const float* dec_bhh = (const float*)d_in[10];
    const float* Wout    = (const float*)d_in[11];
    const float* bout    = (const float*)d_in[12];

    int S = in_sizes[0];                 // encoder sequence length (2048)
    int V = in_sizes[12];                // vocab out (50257)
    int D = out_size / V;                // decoder steps (512)
    int TS = S + D;
    float* out = (float*)d_out;

    int initElems = (TS + 2 > Hdim) ? (TS + 2) : Hdim;
    init_kernel<<<(initElems + 255) / 256, 256>>>(TS);

    xp_gemm<<<dim3((S + 127) / 128, GATES / 128), 256>>>(state, enc_Wih, emb,
                                                         enc_bih, enc_bhh, S);

    recur<<<G_CTAS, 256>>>(enc_Whh, dec_Whh, dec_bih, dec_bhh, S, D);

    out_gemm<<<dim3((V + 127) / 128, (D + 127) / 128), 256>>>(Wout, bout, out,
                                                              S + 1, D, V);

    softmax_rows<<<D, 256>>>(out, V);
}

// round 4
// speedup vs baseline: 1.1398x; 1.1398x over previous
#include <cuda_runtime.h>
#include <math.h>
#include <stdint.h>

#define Hdim   1024
#define Edim   512
#define GATES  4096          // 4*Hdim
#define MAXS   2048
#define MAXD   512
#define G_CTAS 128           // Hdim/8 CTAs, all resident (<=148 SMs)

// ---------------- persistent device state ----------------
__device__ __align__(16) float d_Xp[(size_t)MAXS * GATES];               // encoder input projections (+bias)
__device__ __align__(16) float d_Hbuf[(size_t)(MAXS + MAXD + 1) * Hdim]; // h_t for every step (step-indexed)
__device__ int   d_cnt[MAXS + MAXD + 2];                                 // per-step arrival counters

// ---------------- init: zero counters + h0 ----------------
__global__ void init_kernel(int total_steps) {
    int i = blockIdx.x * blockDim.x + threadIdx.x;
    if (i < total_steps + 2) d_cnt[i] = 0;
    if (i < Hdim) d_Hbuf[i] = 0.0f;
}

// ---------------- Xp GEMM: Xp[t][r] = enc_Wih[r,:] . emb[state[t],:] + enc_b[r] ----------------
__global__ __launch_bounds__(256) void xp_gemm(const int* __restrict__ state,
                                               const float* __restrict__ Wih,
                                               const float* __restrict__ emb,
                                               const float* __restrict__ bih,
                                               const float* __restrict__ bhh,
                                               int S) {
    __shared__ float As[16][132];   // [k][r]
    __shared__ float Bs[16][132];   // [k][t]
    __shared__ int   toks[128];

    int bt = blockIdx.x;            // t tile
    int br = blockIdx.y;            // r tile
    int tid = threadIdx.x;

    if (tid < 128) {
        int t = bt * 128 + tid;
        toks[tid] = (t < S) ? state[t] : 0;
    }
    __syncthreads();

    int tx = tid & 15;              // t dir (8 outputs)
    int ty = tid >> 4;              // r dir (8 outputs)

    float acc[8][8];
#pragma unroll
    for (int i = 0; i < 8; i++)
#pragma unroll
        for (int j = 0; j < 8; j++) acc[i][j] = 0.0f;

    int lrow = tid & 127;
    int kh = (tid >> 7) * 8;

    const float* Aptr = Wih + (size_t)(br * 128 + lrow) * Edim;
    const float* Bptr = emb + (size_t)toks[lrow] * Edim;

    for (int k0 = 0; k0 < Edim; k0 += 16) {
        float4 a0 = *(const float4*)&Aptr[k0 + kh];
        float4 a1 = *(const float4*)&Aptr[k0 + kh + 4];
        float4 b0 = *(const float4*)&Bptr[k0 + kh];
        float4 b1 = *(const float4*)&Bptr[k0 + kh + 4];
        As[kh + 0][lrow] = a0.x; As[kh + 1][lrow] = a0.y;
        As[kh + 2][lrow] = a0.z; As[kh + 3][lrow] = a0.w;
        As[kh + 4][lrow] = a1.x; As[kh + 5][lrow] = a1.y;
        As[kh + 6][lrow] = a1.z; As[kh + 7][lrow] = a1.w;
        Bs[kh + 0][lrow] = b0.x; Bs[kh + 1][lrow] = b0.y;
        Bs[kh + 2][lrow] = b0.z; Bs[kh + 3][lrow] = b0.w;
        Bs[kh + 4][lrow] = b1.x; Bs[kh + 5][lrow] = b1.y;
        Bs[kh + 6][lrow] = b1.z; Bs[kh + 7][lrow] = b1.w;
        __syncthreads();

#pragma unroll
        for (int k = 0; k < 16; k++) {
            float a[8], b[8];
            *(float4*)&a[0] = *(const float4*)&As[k][ty * 8];
            *(float4*)&a[4] = *(const float4*)&As[k][ty * 8 + 4];
            *(float4*)&b[0] = *(const float4*)&Bs[k][tx * 8];
            *(float4*)&b[4] = *(const float4*)&Bs[k][tx * 8 + 4];
#pragma unroll
            for (int i = 0; i < 8; i++)
#pragma unroll
                for (int j = 0; j < 8; j++) acc[i][j] += a[i] * b[j];
        }
        __syncthreads();
    }

    float bias[8];
#pragma unroll
    for (int i = 0; i < 8; i++) {
        int r = br * 128 + ty * 8 + i;
        bias[i] = bih[r] + bhh[r];
    }
#pragma unroll
    for (int j = 0; j < 8; j++) {
        int t = bt * 128 + tx * 8 + j;
        if (t >= S) continue;
        float* orow = d_Xp + (size_t)t * GATES + br * 128 + ty * 8;
        float4 v0 = make_float4(acc[0][j] + bias[0], acc[1][j] + bias[1],
                                acc[2][j] + bias[2], acc[3][j] + bias[3]);
        float4 v1 = make_float4(acc[4][j] + bias[4], acc[5][j] + bias[5],
                                acc[6][j] + bias[6], acc[7][j] + bias[7]);
        *(float4*)&orow[0] = v0;
        *(float4*)&orow[4] = v1;
    }
}

// ---------------- persistent recurrence kernel ----------------
__device__ __forceinline__ float sigmoid_f(float x) { return 1.0f / (1.0f + __expf(-x)); }
// saturating fast tanh: exp overflow -> 1 - 2/inf = 1 ; underflow -> 1 - 2/1... handled:
__device__ __forceinline__ float tanh_f(float x) { return 1.0f - 2.0f / (__expf(2.0f * x) + 1.0f); }

__global__ __launch_bounds__(256, 1) void recur(const float* __restrict__ encWhh,
                                                const float* __restrict__ decWhh,
                                                const float* __restrict__ dbih,
                                                const float* __restrict__ dbhh,
                                                int S, int D) {
    __shared__ float4 hs4[8 * 33];   // padded h (33 float4 per 32-float4 segment)
    __shared__ float  g_s[32];
    __shared__ float  c_s[8];

    int tid = threadIdx.x;
    int b = blockIdx.x;
    int seg = tid & 7;
    int rl = tid >> 3;               // 0..31
    int gate = rl >> 3, q = rl & 7;
    int R = gate * 1024 + b * 8 + q;

    if (tid < 8) c_s[tid] = 0.0f;

    float4 w[32];
    {
        const float4* src = (const float4*)(encWhh + (size_t)R * Hdim + seg * 128);
#pragma unroll
        for (int k = 0; k < 32; k++) w[k] = src[k];
    }
    float decB = 0.0f;
    if (seg == 0) decB = dbih[R] + dbhh[R];

    int TS = S + D;
    for (int t = 0; t < TS; t++) {
        if (t == S) {  // switch to decoder weights
            const float4* src = (const float4*)(decWhh + (size_t)R * Hdim + seg * 128);
#pragma unroll
            for (int k = 0; k < 32; k++) w[k] = src[k];
        }
        if (t > 0) {
            if (tid == 0) {
                int v;
                do {
                    asm volatile("ld.acquire.gpu.u32 %0, [%1];"
                                 : "=r"(v) : "l"(d_cnt + t));
                } while (v < G_CTAS);
            }
        }
        __syncthreads();

        // stage h_t into padded smem (conflict-free, one float4 per thread)
        {
            float4 hv = *(const float4*)(d_Hbuf + (size_t)t * Hdim + tid * 4);
            hs4[tid + (tid >> 5)] = hv;
        }
        float extra = 0.0f;
        if (seg == 0) extra = (t < S) ? d_Xp[(size_t)t * GATES + R] : decB;
        __syncthreads();

        // 128-wide partial dot from register weights
        float a0 = 0, a1 = 0, a2 = 0, a3 = 0;
#pragma unroll
        for (int k = 0; k < 32; k += 2) {
            float4 h0 = hs4[seg * 33 + k];
            float4 h1 = hs4[seg * 33 + k + 1];
            a0 += w[k].x * h0.x;  a1 += w[k].y * h0.y;
            a2 += w[k].z * h0.z;  a3 += w[k].w * h0.w;
            a0 += w[k + 1].x * h1.x;  a1 += w[k + 1].y * h1.y;
            a2 += w[k + 1].z * h1.z;  a3 += w[k + 1].w * h1.w;
        }
        float acc = (a0 + a1) + (a2 + a3);
        acc += __shfl_xor_sync(0xffffffffu, acc, 1);
        acc += __shfl_xor_sync(0xffffffffu, acc, 2);
        acc += __shfl_xor_sync(0xffffffffu, acc, 4);
        if (seg == 0) g_s[rl] = acc + extra;
        __syncthreads();

        // LSTM cell for this CTA's 8 h-indices (warp 0, lanes 0..7)
        if (tid < 8) {
            float i_ = sigmoid_f(g_s[tid]);
            float f_ = sigmoid_f(g_s[8 + tid]);
            float g_ = tanh_f(g_s[16 + tid]);
            float o_ = sigmoid_f(g_s[24 + tid]);
            float c = f_ * c_s[tid] + i_ * g_;
            c_s[tid] = c;
            float h = o_ * tanh_f(c);
            d_Hbuf[(size_t)(t + 1) * Hdim + b * 8 + tid] = h;
        }
        __syncwarp();
        // release-publish this CTA's h for step t+1 (no full membar needed:
        // red.release is A-cumulative over the warp-ordered stores above)
        if (tid == 0)
            asm volatile("red.release.gpu.global.add.u32 [%0], %1;"
                         :: "l"(d_cnt + t + 1), "r"(1) : "memory");
    }
}

// ---------------- output GEMM (tf32 tensor cores) ----------------
// logits[m][n] = Hdec[m,:].Wout[n,:] + bout[n]
// 128x128 tile, BK=32, 256 threads = 8 warps (2m x 4n), each warp 64x32 via
// m16n8k8 tf32 mma. smem stride 36 floats -> conflict-free fragment LDS.
#define OG_STR 36

__device__ __forceinline__ uint32_t f2tf32(float x) {
    uint32_t u;
    asm("cvt.rna.tf32.f32 %0, %1;" : "=r"(u) : "f"(x));
    return u;
}

__device__ __forceinline__ void mma_tf32(float d[4], const uint32_t a[4],
                                         const uint32_t b[2]) {
    asm volatile("mma.sync.aligned.m16n8k8.row.col.f32.tf32.tf32.f32 "
                 "{%0,%1,%2,%3}, {%4,%5,%6,%7}, {%8,%9}, {%0,%1,%2,%3};"
                 : "+f"(d[0]), "+f"(d[1]), "+f"(d[2]), "+f"(d[3])
                 : "r"(a[0]), "r"(a[1]), "r"(a[2]), "r"(a[3]),
                   "r"(b[0]), "r"(b[1]));
}

__global__ __launch_bounds__(256, 2) void out_gemm_tc(const float* __restrict__ Wout,
                                                      const float* __restrict__ bout,
                                                      float* __restrict__ out,
                                                      int hoff, int M, int N) {
    __shared__ uint32_t As[128 * OG_STR];
    __shared__ uint32_t Bs[128 * OG_STR];

    int bn = blockIdx.x, bm = blockIdx.y;
    int tid = threadIdx.x;
    int warp = tid >> 5;
    int lane = tid & 31;
    int grp = lane >> 2;        // 0..7
    int tg  = lane & 3;         // 0..3
    int wm = (warp & 1) * 64;   // warp m offset in tile
    int wn = (warp >> 1) * 32;  // warp n offset in tile

    // load mapping: thread covers row (tid>>1), 16 floats at col part*16
    int lr = tid >> 1;
    int part = (tid & 1) * 16;

    const float* Aptr = d_Hbuf + (size_t)(hoff + bm * 128 + lr) * Hdim + part;
    int nrow = bn * 128 + lr; if (nrow >= N) nrow = N - 1;
    const float* Bptr = Wout + (size_t)nrow * Hdim + part;

    float d[4][4][4];
#pragma unroll
    for (int i = 0; i < 4; i++)
#pragma unroll
        for (int j = 0; j < 4; j++)
#pragma unroll
            for (int k = 0; k < 4; k++) d[i][j][k] = 0.0f;

    for (int k0 = 0; k0 < Hdim; k0 += 32) {
        // global -> smem (tf32-converted)
#pragma unroll
        for (int i = 0; i < 4; i++) {
            float4 av = *(const float4*)(Aptr + k0 + i * 4);
            float4 bv = *(const float4*)(Bptr + k0 + i * 4);
            uint32_t* ad = &As[lr * OG_STR + part + i * 4];
            uint32_t* bd = &Bs[lr * OG_STR + part + i * 4];
            ad[0] = f2tf32(av.x); ad[1] = f2tf32(av.y);
            ad[2] = f2tf32(av.z); ad[3] = f2tf32(av.w);
            bd[0] = f2tf32(bv.x); bd[1] = f2tf32(bv.y);
            bd[2] = f2tf32(bv.z); bd[3] = f2tf32(bv.w);
        }
        __syncthreads();

#pragma unroll
        for (int kk = 0; kk < 32; kk += 8) {
            uint32_t fb[4][2];
#pragma unroll
            for (int na = 0; na < 4; na++) {
                int n = wn + na * 8 + grp;
                fb[na][0] = Bs[n * OG_STR + kk + tg];
                fb[na][1] = Bs[n * OG_STR + kk + tg + 4];
            }
            uint32_t fa[4][4];
#pragma unroll
            for (int ma = 0; ma < 4; ma++) {
                int m = wm + ma * 16;
                fa[ma][0] = As[(m + grp) * OG_STR + kk + tg];
                fa[ma][1] = As[(m + 8 + grp) * OG_STR + kk + tg];
                fa[ma][2] = As[(m + grp) * OG_STR + kk + tg + 4];
                fa[ma][3] = As[(m + 8 + grp) * OG_STR + kk + tg + 4];
            }
#pragma unroll
            for (int ma = 0; ma < 4; ma++)
#pragma unroll
                for (int na = 0; na < 4; na++)
                    mma_tf32(d[ma][na], fa[ma], fb[na]);
        }
        __syncthreads();
    }

    // epilogue: scalar stores (N odd -> rows only 4B aligned)
#pragma unroll
    for (int ma = 0; ma < 4; ma++) {
        int m0 = bm * 128 + wm + ma * 16 + grp;   // M divisible by 128 -> in range
        float* r0 = out + (size_t)m0 * N;
        float* r1 = out + (size_t)(m0 + 8) * N;
#pragma unroll
        for (int na = 0; na < 4; na++) {
            int n0 = bn * 128 + wn + na * 8 + tg * 2;
            if (n0 < N) {
                float bb = bout[n0];
                r0[n0] = d[ma][na][0] + bb;
                r1[n0] = d[ma][na][2] + bb;
            }
            if (n0 + 1 < N) {
                float bb = bout[n0 + 1];
                r0[n0 + 1] = d[ma][na][1] + bb;
                r1[n0 + 1] = d[ma][na][3] + bb;
            }
        }
    }
}

// ---------------- row softmax (in place) ----------------
__global__ void softmax_rows(float* __restrict__ out, int N) {
    int row = blockIdx.x;
    float* p = out + (size_t)row * N;
    int tid = threadIdx.x;
    __shared__ float red[256];

    float mx = -1e30f;
    for (int i = tid; i < N; i += 256) mx = fmaxf(mx, p[i]);
    red[tid] = mx; __syncthreads();
    for (int s = 128; s > 0; s >>= 1) {
        if (tid < s) red[tid] = fmaxf(red[tid], red[tid + s]);
        __syncthreads();
    }
    mx = red[0]; __syncthreads();

    float sum = 0.0f;
    for (int i = tid; i < N; i += 256) sum += __expf(p[i] - mx);
    red[tid] = sum; __syncthreads();
    for (int s = 128; s > 0; s >>= 1) {
        if (tid < s) red[tid] += red[tid + s];
        __syncthreads();
    }
    float inv = 1.0f / red[0];

    for (int i = tid; i < N; i += 256) p[i] = __expf(p[i] - mx) * inv;
}

// ---------------- launch ----------------
extern "C" void kernel_launch(void* const* d_in, const int* in_sizes, int n_in,
                              void* d_out, int out_size) {
    const int*   state   = (const int*)d_in[0];
    const float* emb     = (const float*)d_in[2];
    const float* enc_Wih = (const float*)d_in[3];
    const float* enc_Whh = (const float*)d_in[4];
    const float* enc_bih = (const float*)d_in[5];
    const float* enc_bhh = (const float*)d_in[6];
    const float* dec_Whh = (const float*)d_in[8];
    const float* dec_bih = (const float*)d_in[9];
    const float* dec_bhh = (const float*)d_in[10];
    const float* Wout    = (const float*)d_in[11];
    const float* bout    = (const float*)d_in[12];

    int S = in_sizes[0];                 // encoder sequence length (2048)
    int V = in_sizes[12];                // vocab out (50257)
    int D = out_size / V;                // decoder steps (512)
    int TS = S + D;
    float* out = (float*)d_out;

    int initElems = (TS + 2 > Hdim) ? (TS + 2) : Hdim;
    init_kernel<<<(initElems + 255) / 256, 256>>>(TS);

    xp_gemm<<<dim3((S + 127) / 128, GATES / 128), 256>>>(state, enc_Wih, emb,
                                                         enc_bih, enc_bhh, S);

    recur<<<G_CTAS, 256>>>(enc_Whh, dec_Whh, dec_bih, dec_bhh, S, D);

    out_gemm_tc<<<dim3((V + 127) / 128, (D + 127) / 128), 256>>>(Wout, bout, out,
                                                                 S + 1, D, V);

    softmax_rows<<<D, 256>>>(out, V);
}

// round 6
// speedup vs baseline: 1.6627x; 1.4588x over previous
#include <cuda_runtime.h>
#include <math.h>
#include <stdint.h>

#define Hdim   1024
#define Edim   512
#define GATES  4096          // 4*Hdim
#define MAXS   2048
#define MAXD   512
#define G_CTAS 128           // Hdim/8 CTAs, all resident (<=148 SMs)
#define POISON 0x7FBFFFFFu   // NaN bit pattern; h=o*tanh(c) can never be NaN

// ---------------- persistent device state ----------------
__device__ __align__(16) float d_Xp[(size_t)MAXS * GATES];               // encoder input projections (+bias)
__device__ __align__(16) float d_Hbuf[(size_t)(MAXS + MAXD + 1) * Hdim]; // h_t for every step (step-indexed)

// ---------------- init: zero h0, poison h1..hTS (data-is-the-flag sync) ----------------
__global__ void init_kernel(int total_steps) {
    size_t i = (size_t)blockIdx.x * blockDim.x + threadIdx.x;
    size_t tot = (size_t)(total_steps + 1) * Hdim;
    if (i < Hdim) d_Hbuf[i] = 0.0f;
    else if (i < tot) ((uint32_t*)d_Hbuf)[i] = POISON;
}

// ---------------- Xp GEMM: Xp[t][r] = enc_Wih[r,:] . emb[state[t],:] + enc_b[r] ----------------
__global__ __launch_bounds__(256) void xp_gemm(const int* __restrict__ state,
                                               const float* __restrict__ Wih,
                                               const float* __restrict__ emb,
                                               const float* __restrict__ bih,
                                               const float* __restrict__ bhh,
                                               int S) {
    __shared__ float As[16][132];   // [k][r]
    __shared__ float Bs[16][132];   // [k][t]
    __shared__ int   toks[128];

    int bt = blockIdx.x;            // t tile
    int br = blockIdx.y;            // r tile
    int tid = threadIdx.x;

    if (tid < 128) {
        int t = bt * 128 + tid;
        toks[tid] = (t < S) ? state[t] : 0;
    }
    __syncthreads();

    int tx = tid & 15;              // t dir (8 outputs)
    int ty = tid >> 4;              // r dir (8 outputs)

    float acc[8][8];
#pragma unroll
    for (int i = 0; i < 8; i++)
#pragma unroll
        for (int j = 0; j < 8; j++) acc[i][j] = 0.0f;

    int lrow = tid & 127;
    int kh = (tid >> 7) * 8;

    const float* Aptr = Wih + (size_t)(br * 128 + lrow) * Edim;
    const float* Bptr = emb + (size_t)toks[lrow] * Edim;

    for (int k0 = 0; k0 < Edim; k0 += 16) {
        float4 a0 = *(const float4*)&Aptr[k0 + kh];
        float4 a1 = *(const float4*)&Aptr[k0 + kh + 4];
        float4 b0 = *(const float4*)&Bptr[k0 + kh];
        float4 b1 = *(const float4*)&Bptr[k0 + kh + 4];
        As[kh + 0][lrow] = a0.x; As[kh + 1][lrow] = a0.y;
        As[kh + 2][lrow] = a0.z; As[kh + 3][lrow] = a0.w;
        As[kh + 4][lrow] = a1.x; As[kh + 5][lrow] = a1.y;
        As[kh + 6][lrow] = a1.z; As[kh + 7][lrow] = a1.w;
        Bs[kh + 0][lrow] = b0.x; Bs[kh + 1][lrow] = b0.y;
        Bs[kh + 2][lrow] = b0.z; Bs[kh + 3][lrow] = b0.w;
        Bs[kh + 4][lrow] = b1.x; Bs[kh + 5][lrow] = b1.y;
        Bs[kh + 6][lrow] = b1.z; Bs[kh + 7][lrow] = b1.w;
        __syncthreads();

#pragma unroll
        for (int k = 0; k < 16; k++) {
            float a[8], b[8];
            *(float4*)&a[0] = *(const float4*)&As[k][ty * 8];
            *(float4*)&a[4] = *(const float4*)&As[k][ty * 8 + 4];
            *(float4*)&b[0] = *(const float4*)&Bs[k][tx * 8];
            *(float4*)&b[4] = *(const float4*)&Bs[k][tx * 8 + 4];
#pragma unroll
            for (int i = 0; i < 8; i++)
#pragma unroll
                for (int j = 0; j < 8; j++) acc[i][j] += a[i] * b[j];
        }
        __syncthreads();
    }

    float bias[8];
#pragma unroll
    for (int i = 0; i < 8; i++) {
        int r = br * 128 + ty * 8 + i;
        bias[i] = bih[r] + bhh[r];
    }
#pragma unroll
    for (int j = 0; j < 8; j++) {
        int t = bt * 128 + tx * 8 + j;
        if (t >= S) continue;
        float* orow = d_Xp + (size_t)t * GATES + br * 128 + ty * 8;
        float4 v0 = make_float4(acc[0][j] + bias[0], acc[1][j] + bias[1],
                                acc[2][j] + bias[2], acc[3][j] + bias[3]);
        float4 v1 = make_float4(acc[4][j] + bias[4], acc[5][j] + bias[5],
                                acc[6][j] + bias[6], acc[7][j] + bias[7]);
        *(float4*)&orow[0] = v0;
        *(float4*)&orow[4] = v1;
    }
}

// ---------------- persistent recurrence kernel ----------------
__device__ __forceinline__ float sigmoid_f(float x) { return 1.0f / (1.0f + __expf(-x)); }
__device__ __forceinline__ float tanh_f(float x) { return 1.0f - 2.0f / (__expf(2.0f * x) + 1.0f); }

__global__ __launch_bounds__(256, 1) void recur(const float* __restrict__ encWhh,
                                                const float* __restrict__ decWhh,
                                                const float* __restrict__ dbih,
                                                const float* __restrict__ dbhh,
                                                int S, int D) {
    __shared__ float4 hs4[8 * 33];   // padded h (33 float4 per 32-float4 segment)
    __shared__ float  g_s[32];
    __shared__ float  c_s[8];

    int tid = threadIdx.x;
    int b = blockIdx.x;
    int seg = tid & 7;
    int rl = tid >> 3;               // 0..31
    int gate = rl >> 3, q = rl & 7;
    int R = gate * 1024 + b * 8 + q;

    if (tid < 8) c_s[tid] = 0.0f;

    float4 w[32];
    {
        const float4* src = (const float4*)(encWhh + (size_t)R * Hdim + seg * 128);
#pragma unroll
        for (int k = 0; k < 32; k++) w[k] = src[k];
    }
    float decB = 0.0f;
    if (seg == 0) decB = dbih[R] + dbhh[R];

    int TS = S + D;
    for (int t = 0; t < TS; t++) {
        if (t == S) {  // switch to decoder weights
            const float4* src = (const float4*)(decWhh + (size_t)R * Hdim + seg * 128);
#pragma unroll
            for (int k = 0; k < 32; k++) w[k] = src[k];
        }

        // issue per-row additive term load EARLY (DRAM latency overlaps the poll)
        float extra = 0.0f;
        if (seg == 0) extra = (t < S) ? d_Xp[(size_t)t * GATES + R] : decB;

        // data-is-the-flag: spin on OUR 16B of h_t until all 4 lanes non-poison.
        // (the poll IS the load: no counter, no separate reload)
        uint32_t x0, x1, x2, x3;
        {
            const uint32_t* hp = (const uint32_t*)(d_Hbuf + (size_t)t * Hdim) + tid * 4;
            do {
                asm volatile("ld.relaxed.gpu.global.v4.u32 {%0,%1,%2,%3}, [%4];"
                             : "=r"(x0), "=r"(x1), "=r"(x2), "=r"(x3) : "l"(hp));
            } while (x0 == POISON || x1 == POISON || x2 == POISON || x3 == POISON);
        }
        {
            float4 hv;
            hv.x = __uint_as_float(x0); hv.y = __uint_as_float(x1);
            hv.z = __uint_as_float(x2); hv.w = __uint_as_float(x3);
            hs4[tid + (tid >> 5)] = hv;
        }
        __syncthreads();

        // 128-wide partial dot from register weights
        float a0 = 0, a1 = 0, a2 = 0, a3 = 0;
#pragma unroll
        for (int k = 0; k < 32; k += 2) {
            float4 h0 = hs4[seg * 33 + k];
            float4 h1 = hs4[seg * 33 + k + 1];
            a0 += w[k].x * h0.x;  a1 += w[k].y * h0.y;
            a2 += w[k].z * h0.z;  a3 += w[k].w * h0.w;
            a0 += w[k + 1].x * h1.x;  a1 += w[k + 1].y * h1.y;
            a2 += w[k + 1].z * h1.z;  a3 += w[k + 1].w * h1.w;
        }
        float acc = (a0 + a1) + (a2 + a3);
        acc += __shfl_xor_sync(0xffffffffu, acc, 1);
        acc += __shfl_xor_sync(0xffffffffu, acc, 2);
        acc += __shfl_xor_sync(0xffffffffu, acc, 4);
        if (seg == 0) g_s[rl] = acc + extra;
        __syncthreads();

        // LSTM cell: 32 lanes compute 4 gate activations in parallel, 8 finish
        if (tid < 32) {
            float gv = g_s[tid];
            float act = ((tid >> 3) == 2) ? tanh_f(gv) : sigmoid_f(gv);
            int qq = tid & 7;
            float a_i = __shfl_sync(0xffffffffu, act, qq);
            float a_f = __shfl_sync(0xffffffffu, act, 8 + qq);
            float a_g = __shfl_sync(0xffffffffu, act, 16 + qq);
            float a_o = __shfl_sync(0xffffffffu, act, 24 + qq);
            if (tid < 8) {
                float c = a_f * c_s[tid] + a_i * a_g;
                c_s[tid] = c;
                float h = a_o * tanh_f(c);
                float* hw = d_Hbuf + (size_t)(t + 1) * Hdim + b * 8 + tid;
                asm volatile("st.relaxed.gpu.global.f32 [%0], %1;"
                             :: "l"(hw), "f"(h) : "memory");
            }
        }
        // no global counter, no fence: next iteration's poll is the sync
    }
}

// ---------------- output GEMM (tf32 tensor cores) ----------------
#define OG_STR 36

__device__ __forceinline__ uint32_t f2tf32(float x) {
    uint32_t u;
    asm("cvt.rna.tf32.f32 %0, %1;" : "=r"(u) : "f"(x));
    return u;
}

__device__ __forceinline__ void mma_tf32(float d[4], const uint32_t a[4],
                                         const uint32_t b[2]) {
    asm volatile("mma.sync.aligned.m16n8k8.row.col.f32.tf32.tf32.f32 "
                 "{%0,%1,%2,%3}, {%4,%5,%6,%7}, {%8,%9}, {%0,%1,%2,%3};"
                 : "+f"(d[0]), "+f"(d[1]), "+f"(d[2]), "+f"(d[3])
                 : "r"(a[0]), "r"(a[1]), "r"(a[2]), "r"(a[3]),
                   "r"(b[0]), "r"(b[1]));
}

__global__ __launch_bounds__(256, 2) void out_gemm_tc(const float* __restrict__ Wout,
                                                      const float* __restrict__ bout,
                                                      float* __restrict__ out,
                                                      int hoff, int M, int N) {
    __shared__ uint32_t As[128 * OG_STR];
    __shared__ uint32_t Bs[128 * OG_STR];

    int bn = blockIdx.x, bm = blockIdx.y;
    int tid = threadIdx.x;
    int warp = tid >> 5;
    int lane = tid & 31;
    int grp = lane >> 2;        // 0..7
    int tg  = lane & 3;         // 0..3
    int wm = (warp & 1) * 64;   // warp m offset in tile
    int wn = (warp >> 1) * 32;  // warp n offset in tile

    int lr = tid >> 1;
    int part = (tid & 1) * 16;

    const float* Aptr = d_Hbuf + (size_t)(hoff + bm * 128 + lr) * Hdim + part;
    int nrow = bn * 128 + lr; if (nrow >= N) nrow = N - 1;
    const float* Bptr = Wout + (size_t)nrow * Hdim + part;

    float d[4][4][4];
#pragma unroll
    for (int i = 0; i < 4; i++)
#pragma unroll
        for (int j = 0; j < 4; j++)
#pragma unroll
            for (int k = 0; k < 4; k++) d[i][j][k] = 0.0f;

    for (int k0 = 0; k0 < Hdim; k0 += 32) {
#pragma unroll
        for (int i = 0; i < 4; i++) {
            float4 av = *(const float4*)(Aptr + k0 + i * 4);
            float4 bv = *(const float4*)(Bptr + k0 + i * 4);
            uint32_t* ad = &As[lr * OG_STR + part + i * 4];
            uint32_t* bd = &Bs[lr * OG_STR + part + i * 4];
            ad[0] = f2tf32(av.x); ad[1] = f2tf32(av.y);
            ad[2] = f2tf32(av.z); ad[3] = f2tf32(av.w);
            bd[0] = f2tf32(bv.x); bd[1] = f2tf32(bv.y);
            bd[2] = f2tf32(bv.z); bd[3] = f2tf32(bv.w);
        }
        __syncthreads();

#pragma unroll
        for (int kk = 0; kk < 32; kk += 8) {
            uint32_t fb[4][2];
#pragma unroll
            for (int na = 0; na < 4; na++) {
                int n = wn + na * 8 + grp;
                fb[na][0] = Bs[n * OG_STR + kk + tg];
                fb[na][1] = Bs[n * OG_STR + kk + tg + 4];
            }
            uint32_t fa[4][4];
#pragma unroll
            for (int ma = 0; ma < 4; ma++) {
                int m = wm + ma * 16;
                fa[ma][0] = As[(m + grp) * OG_STR + kk + tg];
                fa[ma][1] = As[(m + 8 + grp) * OG_STR + kk + tg];
                fa[ma][2] = As[(m + grp) * OG_STR + kk + tg + 4];
                fa[ma][3] = As[(m + 8 + grp) * OG_STR + kk + tg + 4];
            }
#pragma unroll
            for (int ma = 0; ma < 4; ma++)
#pragma unroll
                for (int na = 0; na < 4; na++)
                    mma_tf32(d[ma][na], fa[ma], fb[na]);
        }
        __syncthreads();
    }

    // epilogue: scalar stores (N odd -> rows only 4B aligned)
#pragma unroll
    for (int ma = 0; ma < 4; ma++) {
        int m0 = bm * 128 + wm + ma * 16 + grp;
        float* r0 = out + (size_t)m0 * N;
        float* r1 = out + (size_t)(m0 + 8) * N;
#pragma unroll
        for (int na = 0; na < 4; na++) {
            int n0 = bn * 128 + wn + na * 8 + tg * 2;
            if (n0 < N) {
                float bb = bout[n0];
                r0[n0] = d[ma][na][0] + bb;
                r1[n0] = d[ma][na][2] + bb;
            }
            if (n0 + 1 < N) {
                float bb = bout[n0 + 1];
                r0[n0 + 1] = d[ma][na][1] + bb;
                r1[n0 + 1] = d[ma][na][3] + bb;
            }
        }
    }
}

// ---------------- row softmax (in place) ----------------
__global__ void softmax_rows(float* __restrict__ out, int N) {
    int row = blockIdx.x;
    float* p = out + (size_t)row * N;
    int tid = threadIdx.x;
    __shared__ float red[256];

    float mx = -1e30f;
    for (int i = tid; i < N; i += 256) mx = fmaxf(mx, p[i]);
    red[tid] = mx; __syncthreads();
    for (int s = 128; s > 0; s >>= 1) {
        if (tid < s) red[tid] = fmaxf(red[tid], red[tid + s]);
        __syncthreads();
    }
    mx = red[0]; __syncthreads();

    float sum = 0.0f;
    for (int i = tid; i < N; i += 256) sum += __expf(p[i] - mx);
    red[tid] = sum; __syncthreads();
    for (int s = 128; s > 0; s >>= 1) {
        if (tid < s) red[tid] += red[tid + s];
        __syncthreads();
    }
    float inv = 1.0f / red[0];

    for (int i = tid; i < N; i += 256) p[i] = __expf(p[i] - mx) * inv;
}

// ---------------- launch ----------------
extern "C" void kernel_launch(void* const* d_in, const int* in_sizes, int n_in,
                              void* d_out, int out_size) {
    const int*   state   = (const int*)d_in[0];
    const float* emb     = (const float*)d_in[2];
    const float* enc_Wih = (const float*)d_in[3];
    const float* enc_Whh = (const float*)d_in[4];
    const float* enc_bih = (const float*)d_in[5];
    const float* enc_bhh = (const float*)d_in[6];
    const float* dec_Whh = (const float*)d_in[8];
    const float* dec_bih = (const float*)d_in[9];
    const float* dec_bhh = (const float*)d_in[10];
    const float* Wout    = (const float*)d_in[11];
    const float* bout    = (const float*)d_in[12];

    int S = in_sizes[0];                 // encoder sequence length (2048)
    int V = in_sizes[12];                // vocab out (50257)
    int D = out_size / V;                // decoder steps (512)
    int TS = S + D;
    float* out = (float*)d_out;

    size_t initElems = (size_t)(TS + 1) * Hdim;
    init_kernel<<<(int)((initElems + 255) / 256), 256>>>(TS);

    xp_gemm<<<dim3((S + 127) / 128, GATES / 128), 256>>>(state, enc_Wih, emb,
                                                         enc_bih, enc_bhh, S);

    recur<<<G_CTAS, 256>>>(enc_Whh, dec_Whh, dec_bih, dec_bhh, S, D);

    out_gemm_tc<<<dim3((V + 127) / 128, (D + 127) / 128), 256>>>(Wout, bout, out,
                                                                 S + 1, D, V);

    softmax_rows<<<D, 256>>>(out, V);
}